// round 6
// baseline (speedup 1.0000x reference)
#include <cuda_runtime.h>
#include <cstdint>

#define Bc 1024
#define Sc 1024
#define Fc 36
#define Hc 20

typedef unsigned long long u64;

// ---------- packed f32x2 + fast-math helpers ----------
__device__ __forceinline__ u64 pk2(float lo, float hi) {
    u64 r; asm("mov.b64 %0, {%1, %2};" : "=l"(r) : "f"(lo), "f"(hi)); return r;
}
__device__ __forceinline__ void upk2(u64 v, float& lo, float& hi) {
    asm("mov.b64 {%0, %1}, %2;" : "=f"(lo), "=f"(hi) : "l"(v));
}
__device__ __forceinline__ u64 fma2(u64 a, u64 b, u64 c) {
    u64 d; asm("fma.rn.f32x2 %0, %1, %2, %3;" : "=l"(d) : "l"(a), "l"(b), "l"(c)); return d;
}
__device__ __forceinline__ u64 add2(u64 a, u64 b) {
    u64 d; asm("add.rn.f32x2 %0, %1, %2;" : "=l"(d) : "l"(a), "l"(b)); return d;
}
__device__ __forceinline__ float ex2a(float x) { float r; asm("ex2.approx.f32 %0, %1;" : "=f"(r) : "f"(x)); return r; }
__device__ __forceinline__ float rcpa(float x) { float r; asm("rcp.approx.f32 %0, %1;" : "=f"(r) : "f"(x)); return r; }
__device__ __forceinline__ float sigm(float x) { return rcpa(1.0f + ex2a(-1.4426950408889634f * x)); }
__device__ __forceinline__ float tanh_(float x) {
    return fmaf(2.0f, rcpa(1.0f + ex2a(-2.8853900817779268f * x)), -1.0f);
}

// ---------- kernel 1: embedding concat -> origin ----------
__global__ void embed_kernel(const float* __restrict__ x, const void* __restrict__ ohraw,
                             const float* __restrict__ e0, const float* __restrict__ e1,
                             const float* __restrict__ e2, const float* __restrict__ e3,
                             float* __restrict__ org)
{
    int lane = threadIdx.x & 31;
    int probe = ((const int*)ohraw)[2 * lane + 1];
    unsigned m = __ballot_sync(0xFFFFFFFFu, probe != 0);
    bool is64 = (m == 0);

    int idx = blockIdx.x * blockDim.x + threadIdx.x;
    if (idx >= Bc * Sc) return;
    const float4* xr = reinterpret_cast<const float4*>(x + (size_t)idx * 12);
    float4 v0 = xr[0], v1 = xr[1], v2 = xr[2];

    long long i0, i1, i2, i3;
    if (is64) {
        const longlong2* op = reinterpret_cast<const longlong2*>((const long long*)ohraw + (size_t)idx * 4);
        longlong2 a = op[0], b = op[1];
        i0 = a.x; i1 = a.y; i2 = b.x; i3 = b.y;
    } else {
        int4 a = *reinterpret_cast<const int4*>((const int*)ohraw + (size_t)idx * 4);
        i0 = a.x; i1 = a.y; i2 = a.z; i3 = a.w;
    }
    i0 = i0 < 0 ? 0 : (i0 > 9  ? 9  : i0);
    i1 = i1 < 0 ? 0 : (i1 > 19 ? 19 : i1);
    i2 = i2 < 0 ? 0 : (i2 > 49 ? 49 : i2);
    i3 = i3 < 0 ? 0 : (i3 > 99 ? 99 : i3);

    float4* out = reinterpret_cast<float4*>(org + (size_t)idx * 36);
    out[0] = v0; out[1] = v1; out[2] = v2;
    out[3] = *reinterpret_cast<const float4*>(e0 + i0 * 4);
    out[4] = *reinterpret_cast<const float4*>(e1 + i1 * 4);
    const float4* p2 = reinterpret_cast<const float4*>(e2 + i2 * 8);
    out[5] = p2[0]; out[6] = p2[1];
    const float4* p3 = reinterpret_cast<const float4*>(e3 + i3 * 8);
    out[7] = p3[0]; out[8] = p3[1];
}

// ---------- packed partial dots ----------
__device__ __forceinline__ u64 dot18(const u64* __restrict__ xsh, const u64* w, u64 acc0) {
    const ulonglong2* xp = reinterpret_cast<const ulonglong2*>(xsh);
    u64 a0 = acc0, a1 = 0ULL, a2 = 0ULL, a3 = 0ULL;
#pragma unroll
    for (int k = 0; k < 9; k++) {
        ulonglong2 v = xp[k];
        if ((k & 1) == 0) { a0 = fma2(v.x, w[2*k], a0); a1 = fma2(v.y, w[2*k+1], a1); }
        else              { a2 = fma2(v.x, w[2*k], a2); a3 = fma2(v.y, w[2*k+1], a3); }
    }
    return add2(add2(a0, a2), add2(a1, a3));
}
__device__ __forceinline__ u64 dot10(const u64* __restrict__ hsh, const u64* w, u64 acc0) {
    const ulonglong2* hp = reinterpret_cast<const ulonglong2*>(hsh);
    u64 a0 = acc0, a1 = 0ULL, a2 = 0ULL, a3 = 0ULL;
#pragma unroll
    for (int k = 0; k < 5; k++) {
        ulonglong2 v = hp[k];
        if ((k & 1) == 0) { a0 = fma2(v.x, w[2*k], a0); a1 = fma2(v.y, w[2*k+1], a1); }
        else              { a2 = fma2(v.x, w[2*k], a2); a3 = fma2(v.y, w[2*k+1], a3); }
    }
    return add2(add2(a0, a2), add2(a1, a3));
}
__device__ __forceinline__ u64 dot20f(const u64* __restrict__ hsh, const u64* w, u64 acc0) {
    const ulonglong2* hp = reinterpret_cast<const ulonglong2*>(hsh);
    u64 a0 = acc0, a1 = 0ULL, a2 = 0ULL, a3 = 0ULL;
#pragma unroll
    for (int k = 0; k < 10; k++) {
        ulonglong2 v = hp[k];
        if ((k & 1) == 0) { a0 = fma2(v.x, w[2*k], a0); a1 = fma2(v.y, w[2*k+1], a1); }
        else              { a2 = fma2(v.x, w[2*k], a2); a3 = fma2(v.y, w[2*k+1], a3); }
    }
    return add2(add2(a0, a2), add2(a1, a3));
}

// ---------- kernel 2: persistent GRU, 192 threads (6 warps) per block ----------
// Disjoint role lanes (no phase mixing within a warp):
//   gates:    l in [0,120)   — half-rows: row = l%60-ish (half = l/60), 28 u64 weights
//   h-update: l in [128,148)
//   FC:       l in [128,164) — one FC row per lane (decoder only)
//   prefetch: l in [164,173) — encoder only, float4 chunks
// Overlap trick: encoder computes gi(t+1)=Wih*x(t+1) DURING the h(t) update;
// decoder computes gh=Whh*h and x=FC(h) in parallel on disjoint lanes.
__global__ void __launch_bounds__(192) gru_kernel(
    const float* __restrict__ org,
    const float* __restrict__ Wih1, const float* __restrict__ Whh1,
    const float* __restrict__ bih1, const float* __restrict__ bhh1,
    const float* __restrict__ Wih2, const float* __restrict__ Whh2,
    const float* __restrict__ bih2, const float* __restrict__ bhh2,
    const float* __restrict__ Wfc,  const float* __restrict__ bfc,
    float* __restrict__ xs)
{
    const int l = threadIdx.x;
    const int b0 = blockIdx.x * 2;
    const size_t base0 = (size_t)b0 * Sc * Fc;
    const size_t base1 = base0 + (size_t)Sc * Fc;

    __shared__ __align__(16) u64 xring[4][Fc];
    __shared__ __align__(16) u64 hbuf[Hc];
    __shared__ __align__(16) ulonglong2 gRZ[40];   // combined r,z: [row] = {half0, half1}
    __shared__ __align__(16) ulonglong2 gNi[Hc];   // n gate gi part
    __shared__ __align__(16) ulonglong2 gNh[Hc];   // n gate gh part
    __shared__ __align__(16) u64 xdec[Fc];

    const bool gatel = (l < 120);
    const int  half  = (l < 60) ? 0 : 1;
    const int  row   = gatel ? (l - 60 * half) : 0;
    const bool hl    = (l >= 128 && l < 148);
    const int  hj    = l - 128;
    const bool fcl   = (l >= 128 && l < 164);
    const int  fr    = l - 128;
    const bool pfl   = (l >= 164 && l < 173);
    const int  pi    = l - 164;

    u64 wx[18], wh[10], wfcr[20];
    u64 bgi = 0ULL, bnh = 0ULL, bfcr = 0ULL;   // gi-side bias (half0), n-gh bias, fc bias

    // --- encoder gate weights -> regs ---
    if (gatel) {
#pragma unroll
        for (int k = 0; k < 18; k++) { float w = Wih1[row * Fc + half * 18 + k]; wx[k] = pk2(w, w); }
#pragma unroll
        for (int k = 0; k < 10; k++) { float w = Whh1[row * Hc + half * 10 + k]; wh[k] = pk2(w, w); }
        if (half == 0) {
            if (row < 40) { float s = bih1[row] + bhh1[row]; bgi = pk2(s, s); }
            else { float t1 = bih1[row]; bgi = pk2(t1, t1); float t2 = bhh1[row]; bnh = pk2(t2, t2); }
        }
    }
    if (hl) hbuf[hj] = 0ULL;

    // --- prefetch prologue: ring slots 0..3 = x0..x3; qA=x4, qB=x5 ---
    float4 qA0, qA1, qB0, qB1;
    qA0 = qA1 = qB0 = qB1 = make_float4(0.f, 0.f, 0.f, 0.f);
    if (pfl) {
#pragma unroll
        for (int s = 0; s < 4; s++) {
            float4 a = *reinterpret_cast<const float4*>(org + base0 + s * Fc + pi * 4);
            float4 b = *reinterpret_cast<const float4*>(org + base1 + s * Fc + pi * 4);
            ulonglong2* dst = reinterpret_cast<ulonglong2*>(&xring[s][pi * 4]);
            dst[0] = make_ulonglong2(pk2(a.x, b.x), pk2(a.y, b.y));
            dst[1] = make_ulonglong2(pk2(a.z, b.z), pk2(a.w, b.w));
        }
        qA0 = *reinterpret_cast<const float4*>(org + base0 + 4 * Fc + pi * 4);
        qA1 = *reinterpret_cast<const float4*>(org + base1 + 4 * Fc + pi * 4);
        qB0 = *reinterpret_cast<const float4*>(org + base0 + 5 * Fc + pi * 4);
        qB1 = *reinterpret_cast<const float4*>(org + base1 + 5 * Fc + pi * 4);
    }
    __syncthreads();

    // --- prologue: gates(0) from x(0), h(-1)=0 ---
    if (gatel) {
        u64 gi0 = dot18(xring[0] + half * 18, wx, bgi);
        if (row < 40) reinterpret_cast<u64*>(&gRZ[row])[half] = gi0;
        else {
            int m = row - 40;
            reinterpret_cast<u64*>(&gNi[m])[half] = gi0;
            reinterpret_cast<u64*>(&gNh[m])[half] = (half == 0) ? bnh : 0ULL;
        }
    }
    __syncthreads();

    // ================= encoder: S steps, 2 bars/step =================
    u64 gi_reg = 0ULL;
    for (int t = 0; t < Sc; t++) {
        // ---- Phase A: h(t) update  ||  gi(t+1) precompute  ||  prefetch ----
        if (pfl) {
            float4 n0 = make_float4(0.f,0.f,0.f,0.f), n1 = n0;
            if (t + 6 < Sc) {
                n0 = *reinterpret_cast<const float4*>(org + base0 + (size_t)(t + 6) * Fc + pi * 4);
                n1 = *reinterpret_cast<const float4*>(org + base1 + (size_t)(t + 6) * Fc + pi * 4);
            }
            if (t + 4 < Sc) {   // store x(t+4): loaded 2 full steps ago
                int s = (t + 4) & 3;
                ulonglong2* dst = reinterpret_cast<ulonglong2*>(&xring[s][pi * 4]);
                dst[0] = make_ulonglong2(pk2(qA0.x, qA1.x), pk2(qA0.y, qA1.y));
                dst[1] = make_ulonglong2(pk2(qA0.z, qA1.z), pk2(qA0.w, qA1.w));
            }
            qA0 = qB0; qA1 = qB1; qB0 = n0; qB1 = n1;
        }
        if (gatel && (t + 1 < Sc))
            gi_reg = dot18(xring[(t + 1) & 3] + half * 18, wx, bgi);
        if (hl) {
            ulonglong2 vrz = gRZ[hj];        u64 gr  = add2(vrz.x, vrz.y);
            ulonglong2 vz  = gRZ[hj + 20];   u64 gz  = add2(vz.x,  vz.y);
            ulonglong2 vi  = gNi[hj];        u64 gin = add2(vi.x,  vi.y);
            ulonglong2 vh  = gNh[hj];        u64 ghn = add2(vh.x,  vh.y);
            float rx, ry, zx, zy, ax, ay, bx, by, hx, hy;
            upk2(gr, rx, ry); upk2(gz, zx, zy);
            upk2(gin, ax, ay); upk2(ghn, bx, by);
            upk2(hbuf[hj], hx, hy);
            float r0 = sigm(rx), r1 = sigm(ry);
            float z0 = sigm(zx), z1 = sigm(zy);
            float nn0 = tanh_(fmaf(r0, bx, ax));
            float nn1 = tanh_(fmaf(r1, by, ay));
            hbuf[hj] = pk2(fmaf(z0, hx - nn0, nn0), fmaf(z1, hy - nn1, nn1));
        }
        __syncthreads();
        // ---- Phase B: gh(t+1) = Whh*h(t), combine, store gates(t+1) ----
        if (gatel && (t + 1 < Sc)) {
            u64 gh = dot10(hbuf + half * 10, wh, 0ULL);
            if (row < 40) reinterpret_cast<u64*>(&gRZ[row])[half] = add2(gi_reg, gh);
            else {
                int m = row - 40;
                reinterpret_cast<u64*>(&gNi[m])[half] = gi_reg;
                reinterpret_cast<u64*>(&gNh[m])[half] = (half == 0) ? add2(gh, bnh) : gh;
            }
        }
        __syncthreads();
    }

    // ================= phase switch: decoder weights, h = tanh(h) =================
    if (gatel) {
#pragma unroll
        for (int k = 0; k < 18; k++) { float w = Wih2[row * Fc + half * 18 + k]; wx[k] = pk2(w, w); }
#pragma unroll
        for (int k = 0; k < 10; k++) { float w = Whh2[row * Hc + half * 10 + k]; wh[k] = pk2(w, w); }
        if (half == 0) {
            if (row < 40) { float s = bih2[row] + bhh2[row]; bgi = pk2(s, s); }
            else { float t1 = bih2[row]; bgi = pk2(t1, t1); float t2 = bhh2[row]; bnh = pk2(t2, t2); }
        }
    }
    if (fcl) {
#pragma unroll
        for (int k = 0; k < Hc; k++) { float w = Wfc[fr * Hc + k]; wfcr[k] = pk2(w, w); }
        float t = bfc[fr]; bfcr = pk2(t, t);
    }
    if (hl) {
        float hx, hy; upk2(hbuf[hj], hx, hy);
        hbuf[hj] = pk2(tanh_(hx), tanh_(hy));
    }
    __syncthreads();

    // ---- decoder prologue: x0 = tanh(Wfc h + b)  ||  gh(1) = Whh h ----
    u64 gh_reg = 0ULL;
    if (fcl) {
        u64 acc = dot20f(hbuf, wfcr, bfcr);
        float a0, a1; upk2(acc, a0, a1);
        a0 = tanh_(a0); a1 = tanh_(a1);
        xdec[fr] = pk2(a0, a1);
        const size_t rowoff = (size_t)(Sc - 1) * Fc;
        xs[base0 + rowoff + fr] = a0;
        xs[base1 + rowoff + fr] = a1;
    }
    if (gatel) gh_reg = dot10(hbuf + half * 10, wh, 0ULL);
    __syncthreads();
    // gates(1) = gi(x0) + gh
    if (gatel) {
        u64 gi = dot18(xdec + half * 18, wx, bgi);
        if (row < 40) reinterpret_cast<u64*>(&gRZ[row])[half] = add2(gi, gh_reg);
        else {
            int m = row - 40;
            reinterpret_cast<u64*>(&gNi[m])[half] = gi;
            reinterpret_cast<u64*>(&gNh[m])[half] = (half == 0) ? add2(gh_reg, bnh) : gh_reg;
        }
    }
    __syncthreads();

    // ================= decoder: S-1 steps, 3 bars/step =================
    for (int k = 1; k < Sc; k++) {
        // PD_a: h(k) (outer tanh)
        if (hl) {
            ulonglong2 vrz = gRZ[hj];        u64 gr  = add2(vrz.x, vrz.y);
            ulonglong2 vz  = gRZ[hj + 20];   u64 gz  = add2(vz.x,  vz.y);
            ulonglong2 vi  = gNi[hj];        u64 gin = add2(vi.x,  vi.y);
            ulonglong2 vh  = gNh[hj];        u64 ghn = add2(vh.x,  vh.y);
            float rx, ry, zx, zy, ax, ay, bx, by, hx, hy;
            upk2(gr, rx, ry); upk2(gz, zx, zy);
            upk2(gin, ax, ay); upk2(ghn, bx, by);
            upk2(hbuf[hj], hx, hy);
            float r0 = sigm(rx), r1 = sigm(ry);
            float z0 = sigm(zx), z1 = sigm(zy);
            float nn0 = tanh_(fmaf(r0, bx, ax));
            float nn1 = tanh_(fmaf(r1, by, ay));
            float g0 = fmaf(z0, hx - nn0, nn0);
            float g1 = fmaf(z1, hy - nn1, nn1);
            hbuf[hj] = pk2(tanh_(g0), tanh_(g1));
        }
        __syncthreads();
        // PD_b: x(k) = FC(h(k))  ||  gh(k+1) = Whh*h(k)
        if (fcl) {
            u64 acc = dot20f(hbuf, wfcr, bfcr);
            float a0, a1; upk2(acc, a0, a1);
            a0 = tanh_(a0); a1 = tanh_(a1);
            xdec[fr] = pk2(a0, a1);
            const size_t rowoff = (size_t)(Sc - 1 - k) * Fc;
            xs[base0 + rowoff + fr] = a0;
            xs[base1 + rowoff + fr] = a1;
        }
        if (gatel) gh_reg = dot10(hbuf + half * 10, wh, 0ULL);
        __syncthreads();
        // PD_c: gates(k+1) = gi(x(k)) + gh   (harmless extra compute at k=Sc-1)
        if (gatel) {
            u64 gi = dot18(xdec + half * 18, wx, bgi);
            if (row < 40) reinterpret_cast<u64*>(&gRZ[row])[half] = add2(gi, gh_reg);
            else {
                int m = row - 40;
                reinterpret_cast<u64*>(&gNi[m])[half] = gi;
                reinterpret_cast<u64*>(&gNh[m])[half] = (half == 0) ? add2(gh_reg, bnh) : gh_reg;
            }
        }
        __syncthreads();
    }
}

// ---------- launcher ----------
extern "C" void kernel_launch(void* const* d_in, const int* in_sizes, int n_in,
                              void* d_out, int out_size)
{
    const float* x    = (const float*)d_in[0];
    const void*  oh   = d_in[1];
    const float* e0   = (const float*)d_in[2];
    const float* e1   = (const float*)d_in[3];
    const float* e2   = (const float*)d_in[4];
    const float* e3   = (const float*)d_in[5];
    const float* Wih1 = (const float*)d_in[6];
    const float* Whh1 = (const float*)d_in[7];
    const float* bih1 = (const float*)d_in[8];
    const float* bhh1 = (const float*)d_in[9];
    const float* Wih2 = (const float*)d_in[10];
    const float* Whh2 = (const float*)d_in[11];
    const float* bih2 = (const float*)d_in[12];
    const float* bhh2 = (const float*)d_in[13];
    const float* Wfc  = (const float*)d_in[14];
    const float* bfc  = (const float*)d_in[15];

    float* out = (float*)d_out;
    float* org = out;                              // output #1 (origin), also GRU input
    float* xs  = out + (size_t)Bc * Sc * Fc;       // output #2 (decoded, time-flipped)

    embed_kernel<<<(Bc * Sc + 127) / 128, 128>>>(x, oh, e0, e1, e2, e3, org);
    gru_kernel<<<Bc / 2, 192>>>(org, Wih1, Whh1, bih1, bhh1,
                                Wih2, Whh2, bih2, bhh2, Wfc, bfc, xs);
}

// round 7
// speedup vs baseline: 1.8261x; 1.8261x over previous
#include <cuda_runtime.h>
#include <cstdint>

#define Bc 1024
#define Sc 1024
#define Fc 36
#define Hc 20

typedef unsigned long long u64;

// ---------- packed f32x2 + fast-math helpers ----------
__device__ __forceinline__ u64 pk2(float lo, float hi) {
    u64 r; asm("mov.b64 %0, {%1, %2};" : "=l"(r) : "f"(lo), "f"(hi)); return r;
}
__device__ __forceinline__ void upk2(u64 v, float& lo, float& hi) {
    asm("mov.b64 {%0, %1}, %2;" : "=f"(lo), "=f"(hi) : "l"(v));
}
__device__ __forceinline__ u64 fma2(u64 a, u64 b, u64 c) {
    u64 d; asm("fma.rn.f32x2 %0, %1, %2, %3;" : "=l"(d) : "l"(a), "l"(b), "l"(c)); return d;
}
__device__ __forceinline__ u64 add2(u64 a, u64 b) {
    u64 d; asm("add.rn.f32x2 %0, %1, %2;" : "=l"(d) : "l"(a), "l"(b)); return d;
}
__device__ __forceinline__ float ex2a(float x) { float r; asm("ex2.approx.f32 %0, %1;" : "=f"(r) : "f"(x)); return r; }
__device__ __forceinline__ float rcpa(float x) { float r; asm("rcp.approx.f32 %0, %1;" : "=f"(r) : "f"(x)); return r; }
__device__ __forceinline__ float sigm(float x) { return rcpa(1.0f + ex2a(-1.4426950408889634f * x)); }
__device__ __forceinline__ float tanh_(float x) {
    return fmaf(2.0f, rcpa(1.0f + ex2a(-2.8853900817779268f * x)), -1.0f);
}

// ---------- kernel 1: embedding concat -> origin ----------
__global__ void embed_kernel(const float* __restrict__ x, const void* __restrict__ ohraw,
                             const float* __restrict__ e0, const float* __restrict__ e1,
                             const float* __restrict__ e2, const float* __restrict__ e3,
                             float* __restrict__ org)
{
    int lane = threadIdx.x & 31;
    int probe = ((const int*)ohraw)[2 * lane + 1];
    unsigned m = __ballot_sync(0xFFFFFFFFu, probe != 0);
    bool is64 = (m == 0);

    int idx = blockIdx.x * blockDim.x + threadIdx.x;
    if (idx >= Bc * Sc) return;
    const float4* xr = reinterpret_cast<const float4*>(x + (size_t)idx * 12);
    float4 v0 = xr[0], v1 = xr[1], v2 = xr[2];

    long long i0, i1, i2, i3;
    if (is64) {
        const longlong2* op = reinterpret_cast<const longlong2*>((const long long*)ohraw + (size_t)idx * 4);
        longlong2 a = op[0], b = op[1];
        i0 = a.x; i1 = a.y; i2 = b.x; i3 = b.y;
    } else {
        int4 a = *reinterpret_cast<const int4*>((const int*)ohraw + (size_t)idx * 4);
        i0 = a.x; i1 = a.y; i2 = a.z; i3 = a.w;
    }
    i0 = i0 < 0 ? 0 : (i0 > 9  ? 9  : i0);
    i1 = i1 < 0 ? 0 : (i1 > 19 ? 19 : i1);
    i2 = i2 < 0 ? 0 : (i2 > 49 ? 49 : i2);
    i3 = i3 < 0 ? 0 : (i3 > 99 ? 99 : i3);

    float4* out = reinterpret_cast<float4*>(org + (size_t)idx * 36);
    out[0] = v0; out[1] = v1; out[2] = v2;
    out[3] = *reinterpret_cast<const float4*>(e0 + i0 * 4);
    out[4] = *reinterpret_cast<const float4*>(e1 + i1 * 4);
    const float4* p2 = reinterpret_cast<const float4*>(e2 + i2 * 8);
    out[5] = p2[0]; out[6] = p2[1];
    const float4* p3 = reinterpret_cast<const float4*>(e3 + i3 * 8);
    out[7] = p3[0]; out[8] = p3[1];
}

// ---------- packed partial dots ----------
__device__ __forceinline__ u64 dot18(const u64* __restrict__ xsh, const u64* w, u64 acc0) {
    const ulonglong2* xp = reinterpret_cast<const ulonglong2*>(xsh);
    u64 a0 = acc0, a1 = 0ULL, a2 = 0ULL, a3 = 0ULL;
#pragma unroll
    for (int k = 0; k < 9; k++) {
        ulonglong2 v = xp[k];
        if ((k & 1) == 0) { a0 = fma2(v.x, w[2*k], a0); a1 = fma2(v.y, w[2*k+1], a1); }
        else              { a2 = fma2(v.x, w[2*k], a2); a3 = fma2(v.y, w[2*k+1], a3); }
    }
    return add2(add2(a0, a2), add2(a1, a3));
}
__device__ __forceinline__ u64 dot10(const u64* __restrict__ hsh, const u64* w, u64 acc0) {
    const ulonglong2* hp = reinterpret_cast<const ulonglong2*>(hsh);
    u64 a0 = acc0, a1 = 0ULL, a2 = 0ULL, a3 = 0ULL;
#pragma unroll
    for (int k = 0; k < 5; k++) {
        ulonglong2 v = hp[k];
        if ((k & 1) == 0) { a0 = fma2(v.x, w[2*k], a0); a1 = fma2(v.y, w[2*k+1], a1); }
        else              { a2 = fma2(v.x, w[2*k], a2); a3 = fma2(v.y, w[2*k+1], a3); }
    }
    return add2(add2(a0, a2), add2(a1, a3));
}

// ---------- kernel 2: persistent GRU, 128 threads, FORCED 4 blocks/SM ----------
// ONE WAVE: 128 thr * <=128 regs * 4 blocks = 64K regs/SM; 592 slots >= 512 blocks.
// Lane l<120: half-row (half=l/60, row=l%60), 28 weight regs, 28 fma2/phase.
// h-update: lanes 0..19 (overlapped with their gi(t+1) precompute).
// FC (decoder): lanes 20..55, weights in smem (transposed, conflict-free).
// Prefetch: lanes 110..127, float2 chunks, 2 steps of LDG slack.
__global__ void __launch_bounds__(128, 4) gru_kernel(
    const float* __restrict__ org,
    const float* __restrict__ Wih1, const float* __restrict__ Whh1,
    const float* __restrict__ bih1, const float* __restrict__ bhh1,
    const float* __restrict__ Wih2, const float* __restrict__ Whh2,
    const float* __restrict__ bih2, const float* __restrict__ bhh2,
    const float* __restrict__ Wfc,  const float* __restrict__ bfc,
    float* __restrict__ xs)
{
    const int l = threadIdx.x;
    const int b0 = blockIdx.x * 2;
    const size_t base0 = (size_t)b0 * Sc * Fc;
    const size_t base1 = base0 + (size_t)Sc * Fc;

    __shared__ __align__(16) u64 xring[4][Fc];
    __shared__ __align__(16) u64 hbuf[Hc];
    __shared__ __align__(16) u64 prz[40][2];   // combined r,z partials [row][half]
    __shared__ __align__(16) u64 pni[Hc][2];   // n gi partials
    __shared__ __align__(16) u64 pnh[Hc][2];   // n gh partials
    __shared__ __align__(16) u64 xdec[Fc];
    __shared__ __align__(16) u64 wfcT[Hc][Fc]; // transposed FC weights (dup-packed)
    __shared__ __align__(16) u64 bfc2[Fc];

    const bool gl   = (l < 120);
    const int  half = (l < 60) ? 0 : 1;
    const int  row  = gl ? (l - 60 * half) : 0;
    const bool hl   = (l < Hc);
    const bool fcl  = (l >= 20 && l < 56);
    const int  fr   = l - 20;
    const bool pf   = (l >= 110);
    const int  pi   = l - 110;     // 0..17

    u64 wx[18], wh[10];
    u64 bgi = 0ULL, bgh = 0ULL;

    // ---- encoder weights -> regs ----
    if (gl) {
#pragma unroll
        for (int k = 0; k < 18; k++) { float w = Wih1[row * Fc + half * 18 + k]; wx[k] = pk2(w, w); }
#pragma unroll
        for (int k = 0; k < 10; k++) { float w = Whh1[row * Hc + half * 10 + k]; wh[k] = pk2(w, w); }
        if (half == 0) {
            if (row < 40) { float s = bih1[row] + bhh1[row]; bgi = pk2(s, s); }
            else { float a = bih1[row]; bgi = pk2(a, a); float b = bhh1[row]; bgh = pk2(b, b); }
        }
    }
    // ---- FC weights (transposed) + bias -> smem ----
    for (int idx = l; idx < Hc * Fc; idx += 128) {
        int k = idx / Fc, r = idx % Fc;
        float w = Wfc[r * Hc + k];
        wfcT[k][r] = pk2(w, w);
    }
    if (l < Fc) { float t = bfc[l]; bfc2[l] = pk2(t, t); }
    if (hl) hbuf[l] = 0ULL;

    // ---- prefetch prologue: slots 0..2 = x0..x2; qA = x3, qB = x4 ----
    float2 qA0, qA1, qB0, qB1;
    qA0 = qA1 = qB0 = qB1 = make_float2(0.f, 0.f);
    if (pf) {
#pragma unroll
        for (int s = 0; s < 3; s++) {
            float2 a = *reinterpret_cast<const float2*>(org + base0 + s * Fc + 2 * pi);
            float2 b = *reinterpret_cast<const float2*>(org + base1 + s * Fc + 2 * pi);
            *reinterpret_cast<ulonglong2*>(&xring[s][2 * pi]) =
                make_ulonglong2(pk2(a.x, b.x), pk2(a.y, b.y));
        }
        qA0 = *reinterpret_cast<const float2*>(org + base0 + 3 * Fc + 2 * pi);
        qA1 = *reinterpret_cast<const float2*>(org + base1 + 3 * Fc + 2 * pi);
        qB0 = *reinterpret_cast<const float2*>(org + base0 + 4 * Fc + 2 * pi);
        qB1 = *reinterpret_cast<const float2*>(org + base1 + 4 * Fc + 2 * pi);
    }
    __syncthreads();

    // ---- prologue: gates(0) = gi(x0) + gh(h=0 -> bias only) ----
    if (gl) {
        u64 gi0 = dot18(xring[0] + half * 18, wx, bgi);
        u64 gh0 = dot10(hbuf + half * 10, wh, bgh);   // h==0
        if (row < 40) prz[row][half] = add2(gi0, gh0);
        else { pni[row - 40][half] = gi0; pnh[row - 40][half] = gh0; }
    }
    __syncthreads();

    // ================= encoder: S steps, 2 bars/step =================
    u64 gi_reg = 0ULL;
    for (int t = 0; t < Sc; t++) {
        // Phase A: gi(t+1) precompute || prefetch || h(t) update
        if (gl && (t + 1 < Sc))
            gi_reg = dot18(xring[(t + 1) & 3] + half * 18, wx, bgi);
        if (pf) {
            if (t + 3 < Sc) {   // STS x(t+3), loaded 2 steps ago
                *reinterpret_cast<ulonglong2*>(&xring[(t + 3) & 3][2 * pi]) =
                    make_ulonglong2(pk2(qA0.x, qA1.x), pk2(qA0.y, qA1.y));
            }
            qA0 = qB0; qA1 = qB1;
            if (t + 5 < Sc) {
                qB0 = *reinterpret_cast<const float2*>(org + base0 + (size_t)(t + 5) * Fc + 2 * pi);
                qB1 = *reinterpret_cast<const float2*>(org + base1 + (size_t)(t + 5) * Fc + 2 * pi);
            }
        }
        if (hl) {
            ulonglong2 vrz = *reinterpret_cast<ulonglong2*>(prz[l]);
            u64 gr = add2(vrz.x, vrz.y);
            ulonglong2 vzz = *reinterpret_cast<ulonglong2*>(prz[l + 20]);
            u64 gz = add2(vzz.x, vzz.y);
            ulonglong2 vni = *reinterpret_cast<ulonglong2*>(pni[l]);
            u64 gin = add2(vni.x, vni.y);
            ulonglong2 vnh = *reinterpret_cast<ulonglong2*>(pnh[l]);
            u64 ghn = add2(vnh.x, vnh.y);
            float rx, ry, zx, zy, ax, ay, bx, by, hx, hy;
            upk2(gr, rx, ry); upk2(gz, zx, zy);
            upk2(gin, ax, ay); upk2(ghn, bx, by);
            upk2(hbuf[l], hx, hy);
            float r0 = sigm(rx), r1 = sigm(ry);
            float z0 = sigm(zx), z1 = sigm(zy);
            float nn0 = tanh_(fmaf(r0, bx, ax));
            float nn1 = tanh_(fmaf(r1, by, ay));
            hbuf[l] = pk2(fmaf(z0, hx - nn0, nn0), fmaf(z1, hy - nn1, nn1));
        }
        __syncthreads();
        // Phase B: gh(t+1) = Whh*h(t); combine+store gates(t+1)
        if (gl && (t + 1 < Sc)) {
            u64 gh = dot10(hbuf + half * 10, wh, bgh);
            if (row < 40) prz[row][half] = add2(gi_reg, gh);
            else { pni[row - 40][half] = gi_reg; pnh[row - 40][half] = gh; }
        }
        __syncthreads();
    }

    // ================= phase switch =================
    if (gl) {
#pragma unroll
        for (int k = 0; k < 18; k++) { float w = Wih2[row * Fc + half * 18 + k]; wx[k] = pk2(w, w); }
#pragma unroll
        for (int k = 0; k < 10; k++) { float w = Whh2[row * Hc + half * 10 + k]; wh[k] = pk2(w, w); }
        bgi = 0ULL; bgh = 0ULL;
        if (half == 0) {
            if (row < 40) { float s = bih2[row] + bhh2[row]; bgi = pk2(s, s); }
            else { float a = bih2[row]; bgi = pk2(a, a); float b = bhh2[row]; bgh = pk2(b, b); }
        }
    }
    if (hl) {
        float hx, hy; upk2(hbuf[l], hx, hy);
        hbuf[l] = pk2(tanh_(hx), tanh_(hy));
    }
    __syncthreads();

    // ---- decoder prologue: x0 = tanh(FC(h)) || gh(1) ----
    u64 gh_reg = 0ULL;
    if (gl) gh_reg = dot10(hbuf + half * 10, wh, bgh);
    if (fcl) {
        const ulonglong2* hp = reinterpret_cast<const ulonglong2*>(hbuf);
        u64 a0 = bfc2[fr], a1 = 0ULL;
#pragma unroll
        for (int k = 0; k < 10; k++) {
            ulonglong2 hv = hp[k];
            a0 = fma2(hv.x, wfcT[2*k][fr], a0);
            a1 = fma2(hv.y, wfcT[2*k+1][fr], a1);
        }
        u64 acc = add2(a0, a1);
        float v0, v1; upk2(acc, v0, v1);
        v0 = tanh_(v0); v1 = tanh_(v1);
        xdec[fr] = pk2(v0, v1);
        const size_t rowoff = (size_t)(Sc - 1) * Fc;
        xs[base0 + rowoff + fr] = v0;
        xs[base1 + rowoff + fr] = v1;
    }
    __syncthreads();
    if (gl) {   // gates(1) = gi(x0) + gh
        u64 gi = dot18(xdec + half * 18, wx, bgi);
        if (row < 40) prz[row][half] = add2(gi, gh_reg);
        else { pni[row - 40][half] = gi; pnh[row - 40][half] = gh_reg; }
    }
    __syncthreads();

    // ================= decoder: S-1 steps, 3 bars/step =================
    for (int k = 1; k < Sc; k++) {
        // a: h(k) with outer tanh
        if (hl) {
            ulonglong2 vrz = *reinterpret_cast<ulonglong2*>(prz[l]);
            u64 gr = add2(vrz.x, vrz.y);
            ulonglong2 vzz = *reinterpret_cast<ulonglong2*>(prz[l + 20]);
            u64 gz = add2(vzz.x, vzz.y);
            ulonglong2 vni = *reinterpret_cast<ulonglong2*>(pni[l]);
            u64 gin = add2(vni.x, vni.y);
            ulonglong2 vnh = *reinterpret_cast<ulonglong2*>(pnh[l]);
            u64 ghn = add2(vnh.x, vnh.y);
            float rx, ry, zx, zy, ax, ay, bx, by, hx, hy;
            upk2(gr, rx, ry); upk2(gz, zx, zy);
            upk2(gin, ax, ay); upk2(ghn, bx, by);
            upk2(hbuf[l], hx, hy);
            float r0 = sigm(rx), r1 = sigm(ry);
            float z0 = sigm(zx), z1 = sigm(zy);
            float nn0 = tanh_(fmaf(r0, bx, ax));
            float nn1 = tanh_(fmaf(r1, by, ay));
            float g0 = fmaf(z0, hx - nn0, nn0);
            float g1 = fmaf(z1, hy - nn1, nn1);
            hbuf[l] = pk2(tanh_(g0), tanh_(g1));
        }
        __syncthreads();
        // b: gh(k+1) on all gate lanes; FC -> x(k) on lanes 20..55
        if (gl) gh_reg = dot10(hbuf + half * 10, wh, bgh);
        if (fcl) {
            const ulonglong2* hp = reinterpret_cast<const ulonglong2*>(hbuf);
            u64 a0 = bfc2[fr], a1 = 0ULL;
#pragma unroll
            for (int kk = 0; kk < 10; kk++) {
                ulonglong2 hv = hp[kk];
                a0 = fma2(hv.x, wfcT[2*kk][fr], a0);
                a1 = fma2(hv.y, wfcT[2*kk+1][fr], a1);
            }
            u64 acc = add2(a0, a1);
            float v0, v1; upk2(acc, v0, v1);
            v0 = tanh_(v0); v1 = tanh_(v1);
            xdec[fr] = pk2(v0, v1);
            const size_t rowoff = (size_t)(Sc - 1 - k) * Fc;
            xs[base0 + rowoff + fr] = v0;
            xs[base1 + rowoff + fr] = v1;
        }
        __syncthreads();
        // c: gates(k+1) = gi(x(k)) + gh  (k=Sc-1: harmless dead compute)
        if (gl) {
            u64 gi = dot18(xdec + half * 18, wx, bgi);
            if (row < 40) prz[row][half] = add2(gi, gh_reg);
            else { pni[row - 40][half] = gi; pnh[row - 40][half] = gh_reg; }
        }
        __syncthreads();
    }
}

// ---------- launcher ----------
extern "C" void kernel_launch(void* const* d_in, const int* in_sizes, int n_in,
                              void* d_out, int out_size)
{
    const float* x    = (const float*)d_in[0];
    const void*  oh   = d_in[1];
    const float* e0   = (const float*)d_in[2];
    const float* e1   = (const float*)d_in[3];
    const float* e2   = (const float*)d_in[4];
    const float* e3   = (const float*)d_in[5];
    const float* Wih1 = (const float*)d_in[6];
    const float* Whh1 = (const float*)d_in[7];
    const float* bih1 = (const float*)d_in[8];
    const float* bhh1 = (const float*)d_in[9];
    const float* Wih2 = (const float*)d_in[10];
    const float* Whh2 = (const float*)d_in[11];
    const float* bih2 = (const float*)d_in[12];
    const float* bhh2 = (const float*)d_in[13];
    const float* Wfc  = (const float*)d_in[14];
    const float* bfc  = (const float*)d_in[15];

    float* out = (float*)d_out;
    float* org = out;                              // output #1 (origin), also GRU input
    float* xs  = out + (size_t)Bc * Sc * Fc;       // output #2 (decoded, time-flipped)

    embed_kernel<<<(Bc * Sc + 127) / 128, 128>>>(x, oh, e0, e1, e2, e3, org);
    gru_kernel<<<Bc / 2, 128>>>(org, Wih1, Whh1, bih1, bhh1,
                                Wih2, Whh2, bih2, bhh2, Wfc, bfc, xs);
}

// round 8
// speedup vs baseline: 1.8362x; 1.0055x over previous
#include <cuda_runtime.h>
#include <cstdint>

#define Bc 1024
#define Sc 1024
#define Fc 36
#define Hc 20
#define Pc 512   // chain pairs (2 batch elems packed in f32x2)

typedef unsigned long long u64;

// 240MB scratch: precomputed encoder gi = Wih1 @ x + folded biases
__device__ u64 g_gi[(size_t)Pc * Sc * 60];

// ---------- packed f32x2 + fast-math helpers ----------
__device__ __forceinline__ u64 pk2(float lo, float hi) {
    u64 r; asm("mov.b64 %0, {%1, %2};" : "=l"(r) : "f"(lo), "f"(hi)); return r;
}
__device__ __forceinline__ void upk2(u64 v, float& lo, float& hi) {
    asm("mov.b64 {%0, %1}, %2;" : "=f"(lo), "=f"(hi) : "l"(v));
}
__device__ __forceinline__ u64 fma2(u64 a, u64 b, u64 c) {
    u64 d; asm("fma.rn.f32x2 %0, %1, %2, %3;" : "=l"(d) : "l"(a), "l"(b), "l"(c)); return d;
}
__device__ __forceinline__ u64 add2(u64 a, u64 b) {
    u64 d; asm("add.rn.f32x2 %0, %1, %2;" : "=l"(d) : "l"(a), "l"(b)); return d;
}
__device__ __forceinline__ float ex2a(float x) { float r; asm("ex2.approx.f32 %0, %1;" : "=f"(r) : "f"(x)); return r; }
__device__ __forceinline__ float rcpa(float x) { float r; asm("rcp.approx.f32 %0, %1;" : "=f"(r) : "f"(x)); return r; }
__device__ __forceinline__ float sigm(float x) { return rcpa(1.0f + ex2a(-1.4426950408889634f * x)); }
__device__ __forceinline__ float tanh_(float x) {
    return fmaf(2.0f, rcpa(1.0f + ex2a(-2.8853900817779268f * x)), -1.0f);
}

// ---------- kernel 1: embedding concat -> origin ----------
__global__ void embed_kernel(const float* __restrict__ x, const void* __restrict__ ohraw,
                             const float* __restrict__ e0, const float* __restrict__ e1,
                             const float* __restrict__ e2, const float* __restrict__ e3,
                             float* __restrict__ org)
{
    int lane = threadIdx.x & 31;
    int probe = ((const int*)ohraw)[2 * lane + 1];
    unsigned m = __ballot_sync(0xFFFFFFFFu, probe != 0);
    bool is64 = (m == 0);

    int idx = blockIdx.x * blockDim.x + threadIdx.x;
    if (idx >= Bc * Sc) return;
    const float4* xr = reinterpret_cast<const float4*>(x + (size_t)idx * 12);
    float4 v0 = xr[0], v1 = xr[1], v2 = xr[2];

    long long i0, i1, i2, i3;
    if (is64) {
        const longlong2* op = reinterpret_cast<const longlong2*>((const long long*)ohraw + (size_t)idx * 4);
        longlong2 a = op[0], b = op[1];
        i0 = a.x; i1 = a.y; i2 = b.x; i3 = b.y;
    } else {
        int4 a = *reinterpret_cast<const int4*>((const int*)ohraw + (size_t)idx * 4);
        i0 = a.x; i1 = a.y; i2 = a.z; i3 = a.w;
    }
    i0 = i0 < 0 ? 0 : (i0 > 9  ? 9  : i0);
    i1 = i1 < 0 ? 0 : (i1 > 19 ? 19 : i1);
    i2 = i2 < 0 ? 0 : (i2 > 49 ? 49 : i2);
    i3 = i3 < 0 ? 0 : (i3 > 99 ? 99 : i3);

    float4* out = reinterpret_cast<float4*>(org + (size_t)idx * 36);
    out[0] = v0; out[1] = v1; out[2] = v2;
    out[3] = *reinterpret_cast<const float4*>(e0 + i0 * 4);
    out[4] = *reinterpret_cast<const float4*>(e1 + i1 * 4);
    const float4* p2 = reinterpret_cast<const float4*>(e2 + i2 * 8);
    out[5] = p2[0]; out[6] = p2[1];
    const float4* p3 = reinterpret_cast<const float4*>(e3 + i3 * 8);
    out[7] = p3[0]; out[8] = p3[1];
}

// ---------- kernel 2: GI precompute (throughput GEMM-ish) ----------
// gi[p][t][row] = Wih1[row,:] . x_pair(p,t)  + bih1[row] (+bhh1[row] for r,z rows)
__global__ void __launch_bounds__(128) gi_kernel(
    const float* __restrict__ org,
    const float* __restrict__ Wih1, const float* __restrict__ bih1,
    const float* __restrict__ bhh1)
{
    __shared__ __align__(16) u64 wsm[60][36];
    __shared__ u64 bsm[60];
    const int tid = threadIdx.x;
    const int p = blockIdx.y;
    for (int i = tid; i < 60 * 36; i += 128) {
        float w = Wih1[i];
        wsm[i / 36][i % 36] = pk2(w, w);
    }
    if (tid < 60) {
        float b = bih1[tid] + (tid < 40 ? bhh1[tid] : 0.0f);
        bsm[tid] = pk2(b, b);
    }
    __syncthreads();

    const int t = blockIdx.x * 128 + tid;
    const size_t off0 = ((size_t)(2 * p) * Sc + t) * Fc;
    const size_t off1 = off0 + (size_t)Sc * Fc;
    u64 xr[36];
#pragma unroll
    for (int k = 0; k < 9; k++) {
        float4 a = *reinterpret_cast<const float4*>(org + off0 + 4 * k);
        float4 b = *reinterpret_cast<const float4*>(org + off1 + 4 * k);
        xr[4*k+0] = pk2(a.x, b.x); xr[4*k+1] = pk2(a.y, b.y);
        xr[4*k+2] = pk2(a.z, b.z); xr[4*k+3] = pk2(a.w, b.w);
    }
    u64* gout = g_gi + ((size_t)p * Sc + t) * 60;
#pragma unroll 2
    for (int r = 0; r < 60; r += 2) {
        const ulonglong2* w0 = reinterpret_cast<const ulonglong2*>(wsm[r]);
        const ulonglong2* w1 = reinterpret_cast<const ulonglong2*>(wsm[r + 1]);
        u64 a0 = bsm[r], a1 = 0ULL, b0 = bsm[r + 1], b1 = 0ULL;
#pragma unroll
        for (int k = 0; k < 18; k++) {
            ulonglong2 wa = w0[k], wb = w1[k];
            a0 = fma2(xr[2*k], wa.x, a0); a1 = fma2(xr[2*k+1], wa.y, a1);
            b0 = fma2(xr[2*k], wb.x, b0); b1 = fma2(xr[2*k+1], wb.y, b1);
        }
        *reinterpret_cast<ulonglong2*>(gout + r) =
            make_ulonglong2(add2(a0, a1), add2(b0, b1));
    }
}

// ---------- packed partial dots ----------
__device__ __forceinline__ u64 dot18(const u64* __restrict__ xsh, const u64* w, u64 acc0) {
    const ulonglong2* xp = reinterpret_cast<const ulonglong2*>(xsh);
    u64 a0 = acc0, a1 = 0ULL, a2 = 0ULL, a3 = 0ULL;
#pragma unroll
    for (int k = 0; k < 9; k++) {
        ulonglong2 v = xp[k];
        if ((k & 1) == 0) { a0 = fma2(v.x, w[2*k], a0); a1 = fma2(v.y, w[2*k+1], a1); }
        else              { a2 = fma2(v.x, w[2*k], a2); a3 = fma2(v.y, w[2*k+1], a3); }
    }
    return add2(add2(a0, a2), add2(a1, a3));
}
__device__ __forceinline__ u64 dot10(const u64* __restrict__ hsh, const u64* w, u64 acc0) {
    const ulonglong2* hp = reinterpret_cast<const ulonglong2*>(hsh);
    u64 a0 = acc0, a1 = 0ULL, a2 = 0ULL, a3 = 0ULL;
#pragma unroll
    for (int k = 0; k < 5; k++) {
        ulonglong2 v = hp[k];
        if ((k & 1) == 0) { a0 = fma2(v.x, w[2*k], a0); a1 = fma2(v.y, w[2*k+1], a1); }
        else              { a2 = fma2(v.x, w[2*k], a2); a3 = fma2(v.y, w[2*k+1], a3); }
    }
    return add2(add2(a0, a2), add2(a1, a3));
}
__device__ __forceinline__ u64 dot20f(const u64* __restrict__ hsh, const u64* w, u64 acc0) {
    const ulonglong2* hp = reinterpret_cast<const ulonglong2*>(hsh);
    u64 a0 = acc0, a1 = 0ULL, a2 = 0ULL, a3 = 0ULL;
#pragma unroll
    for (int k = 0; k < 10; k++) {
        ulonglong2 v = hp[k];
        if ((k & 1) == 0) { a0 = fma2(v.x, w[2*k], a0); a1 = fma2(v.y, w[2*k+1], a1); }
        else              { a2 = fma2(v.x, w[2*k], a2); a3 = fma2(v.y, w[2*k+1], a3); }
    }
    return add2(add2(a0, a2), add2(a1, a3));
}

// ---------- kernel 3: persistent GRU, 128 thr, 4 blocks/SM (one wave) ----------
// Encoder: gi precomputed -> per-step only LDG gi + dot20 gh + h-update.
// h-warp and FC-warps rotate with blockIdx&3 so co-resident blocks use
// different SMSPs for their MUFU-heavy chains.
__global__ void __launch_bounds__(128, 4) gru_kernel(
    const float* __restrict__ Whh1, const float* __restrict__ bhh1,
    const float* __restrict__ Wih2, const float* __restrict__ Whh2,
    const float* __restrict__ bih2, const float* __restrict__ bhh2,
    const float* __restrict__ Wfc,  const float* __restrict__ bfc,
    float* __restrict__ xs)
{
    const int l = threadIdx.x;
    const int p = blockIdx.x;
    const size_t base0 = (size_t)(2 * p) * Sc * Fc;
    const size_t base1 = base0 + (size_t)Sc * Fc;
    const int hw  = p & 3;
    const int gw1 = (hw + 1) & 3, gw2 = (hw + 2) & 3;
    const int ws = l >> 5, li = l & 31;

    __shared__ __align__(16) u64 hbuf[Hc];
    __shared__ __align__(16) u64 prz[40][2];
    __shared__ __align__(16) u64 pni[Hc][2];
    __shared__ __align__(16) u64 pnh[Hc][2];
    __shared__ __align__(16) u64 xdec[Fc];
    __shared__ __align__(16) u64 wfcT[Hc][Fc];
    __shared__ __align__(16) u64 bfc2[Fc];

    const bool hl   = (ws == hw) && (li < Hc);
    const int  hj   = li;
    const bool encg = ((ws == gw1) || (ws == gw2)) && (li < 30);
    const int  grow = ((ws == gw2) ? 30 : 0) + li;
    const bool fc1  = (ws == gw1) && (li < 18);
    const bool fc2  = (ws == gw2) && (li < 18);
    const bool fcl  = fc1 || fc2;
    const int  fr   = (fc2 ? 18 : 0) + li;
    const bool dg   = (l < 120);
    const int  half = (l < 60) ? 0 : 1;
    const int  drow = l - 60 * half;

    u64 wreg[28];                       // enc: wh full row in [0..19]; dec: wx[0..17], wh[18..27]
    u64 breg = 0ULL, bgi = 0ULL, bgh = 0ULL;

    // encoder Whh full rows -> regs
    if (encg) {
#pragma unroll
        for (int k = 0; k < Hc; k++) { float w = Whh1[grow * Hc + k]; wreg[k] = pk2(w, w); }
        if (grow >= 40) { float b = bhh1[grow]; breg = pk2(b, b); }
    }
    // FC weights (transposed) + bias -> smem
    for (int i = l; i < Hc * Fc; i += 128) {
        int k = i / Fc, r = i % Fc;
        float w = Wfc[r * Hc + k];
        wfcT[k][r] = pk2(w, w);
    }
    if (l < Fc) { float b = bfc[l]; bfc2[l] = pk2(b, b); }
    if (hl) hbuf[hj] = 0ULL;
    if (l < 40) prz[l][1] = 0ULL;                         // encoder writes only half 0
    if (l >= 40 && l < 60) { pni[l - 40][1] = 0ULL; pnh[l - 40][1] = 0ULL; }

    // gates(0): gi(0) (biases folded) + gh(h=0) ; prefetch gi(1), gi(2)
    const u64* gibase = g_gi + (size_t)p * Sc * 60;
    u64 gcur = 0ULL, gnext = 0ULL, gnew = 0ULL;
    if (encg) {
        u64 g0 = gibase[grow];
        if (grow < 40) prz[grow][0] = g0;
        else { pni[grow - 40][0] = g0; pnh[grow - 40][0] = breg; }
        gcur  = gibase[60 + grow];
        gnext = gibase[120 + grow];
    }
    __syncthreads();

    // ================= encoder: S steps, 2 bars/step =================
    for (int t = 0; t < Sc; t++) {
        // Phase A: h(t) update (hw warp) || gi(t+3) prefetch (gate warps)
        if (encg) {
            int tf = t + 3; if (tf > Sc - 1) tf = Sc - 1;
            gnew = gibase[(size_t)tf * 60 + grow];
        }
        if (hl) {
            ulonglong2 vrz = *reinterpret_cast<ulonglong2*>(prz[hj]);
            u64 gr = add2(vrz.x, vrz.y);
            ulonglong2 vzz = *reinterpret_cast<ulonglong2*>(prz[hj + 20]);
            u64 gz = add2(vzz.x, vzz.y);
            ulonglong2 vni = *reinterpret_cast<ulonglong2*>(pni[hj]);
            u64 gin = add2(vni.x, vni.y);
            ulonglong2 vnh = *reinterpret_cast<ulonglong2*>(pnh[hj]);
            u64 ghn = add2(vnh.x, vnh.y);
            float rx, ry, zx, zy, ax, ay, bx, by, hx, hy;
            upk2(gr, rx, ry); upk2(gz, zx, zy);
            upk2(gin, ax, ay); upk2(ghn, bx, by);
            upk2(hbuf[hj], hx, hy);
            float r0 = sigm(rx), r1 = sigm(ry);
            float z0 = sigm(zx), z1 = sigm(zy);
            float nn0 = tanh_(fmaf(r0, bx, ax));
            float nn1 = tanh_(fmaf(r1, by, ay));
            hbuf[hj] = pk2(fmaf(z0, hx - nn0, nn0), fmaf(z1, hy - nn1, nn1));
        }
        __syncthreads();
        // Phase B: gh(t+1) = Whh*h(t); combine with precomputed gi(t+1)
        if (encg && (t + 1 < Sc)) {
            u64 gh = dot20f(hbuf, wreg, (grow >= 40) ? breg : 0ULL);
            if (grow < 40) prz[grow][0] = add2(gcur, gh);
            else { pni[grow - 40][0] = gcur; pnh[grow - 40][0] = gh; }
            gcur = gnext; gnext = gnew;
        }
        __syncthreads();
    }

    // ================= phase switch =================
    if (dg) {
#pragma unroll
        for (int k = 0; k < 18; k++) { float w = Wih2[drow * Fc + half * 18 + k]; wreg[k] = pk2(w, w); }
#pragma unroll
        for (int k = 0; k < 10; k++) { float w = Whh2[drow * Hc + half * 10 + k]; wreg[18 + k] = pk2(w, w); }
        if (half == 0) {
            if (drow < 40) { float s = bih2[drow] + bhh2[drow]; bgi = pk2(s, s); }
            else { float a = bih2[drow]; bgi = pk2(a, a); float b = bhh2[drow]; bgh = pk2(b, b); }
        }
    }
    if (hl) {
        float hx, hy; upk2(hbuf[hj], hx, hy);
        hbuf[hj] = pk2(tanh_(hx), tanh_(hy));
    }
    __syncthreads();

    // ---- decoder prologue: x0 = tanh(FC(h)) || gh(1) ----
    u64 gh_reg = 0ULL;
    if (dg) gh_reg = dot10(hbuf + half * 10, wreg + 18, bgh);
    if (fcl) {
        const ulonglong2* hp = reinterpret_cast<const ulonglong2*>(hbuf);
        u64 a0 = bfc2[fr], a1 = 0ULL;
#pragma unroll
        for (int kk = 0; kk < 10; kk++) {
            ulonglong2 hv = hp[kk];
            a0 = fma2(hv.x, wfcT[2*kk][fr], a0);
            a1 = fma2(hv.y, wfcT[2*kk+1][fr], a1);
        }
        u64 acc = add2(a0, a1);
        float v0, v1; upk2(acc, v0, v1);
        v0 = tanh_(v0); v1 = tanh_(v1);
        xdec[fr] = pk2(v0, v1);
        const size_t rowoff = (size_t)(Sc - 1) * Fc;
        xs[base0 + rowoff + fr] = v0;
        xs[base1 + rowoff + fr] = v1;
    }
    __syncthreads();
    if (dg) {   // gates(1) = gi(x0) + gh
        u64 gi = dot18(xdec + half * 18, wreg, bgi);
        if (drow < 40) prz[drow][half] = add2(gi, gh_reg);
        else { pni[drow - 40][half] = gi; pnh[drow - 40][half] = gh_reg; }
    }
    __syncthreads();

    // ================= decoder: S-1 steps, 3 bars/step =================
    for (int k = 1; k < Sc; k++) {
        // a: h(k) with outer tanh
        if (hl) {
            ulonglong2 vrz = *reinterpret_cast<ulonglong2*>(prz[hj]);
            u64 gr = add2(vrz.x, vrz.y);
            ulonglong2 vzz = *reinterpret_cast<ulonglong2*>(prz[hj + 20]);
            u64 gz = add2(vzz.x, vzz.y);
            ulonglong2 vni = *reinterpret_cast<ulonglong2*>(pni[hj]);
            u64 gin = add2(vni.x, vni.y);
            ulonglong2 vnh = *reinterpret_cast<ulonglong2*>(pnh[hj]);
            u64 ghn = add2(vnh.x, vnh.y);
            float rx, ry, zx, zy, ax, ay, bx, by, hx, hy;
            upk2(gr, rx, ry); upk2(gz, zx, zy);
            upk2(gin, ax, ay); upk2(ghn, bx, by);
            upk2(hbuf[hj], hx, hy);
            float r0 = sigm(rx), r1 = sigm(ry);
            float z0 = sigm(zx), z1 = sigm(zy);
            float nn0 = tanh_(fmaf(r0, bx, ax));
            float nn1 = tanh_(fmaf(r1, by, ay));
            float g0 = fmaf(z0, hx - nn0, nn0);
            float g1 = fmaf(z1, hy - nn1, nn1);
            hbuf[hj] = pk2(tanh_(g0), tanh_(g1));
        }
        __syncthreads();
        // b: gh(k+1) on gate lanes || FC -> x(k) on rotated FC lanes
        if (dg) gh_reg = dot10(hbuf + half * 10, wreg + 18, bgh);
        if (fcl) {
            const ulonglong2* hp = reinterpret_cast<const ulonglong2*>(hbuf);
            u64 a0 = bfc2[fr], a1 = 0ULL;
#pragma unroll
            for (int kk = 0; kk < 10; kk++) {
                ulonglong2 hv = hp[kk];
                a0 = fma2(hv.x, wfcT[2*kk][fr], a0);
                a1 = fma2(hv.y, wfcT[2*kk+1][fr], a1);
            }
            u64 acc = add2(a0, a1);
            float v0, v1; upk2(acc, v0, v1);
            v0 = tanh_(v0); v1 = tanh_(v1);
            xdec[fr] = pk2(v0, v1);
            const size_t rowoff = (size_t)(Sc - 1 - k) * Fc;
            xs[base0 + rowoff + fr] = v0;
            xs[base1 + rowoff + fr] = v1;
        }
        __syncthreads();
        // c: gates(k+1) = gi(x(k)) + gh  (k=Sc-1: harmless dead compute)
        if (dg) {
            u64 gi = dot18(xdec + half * 18, wreg, bgi);
            if (drow < 40) prz[drow][half] = add2(gi, gh_reg);
            else { pni[drow - 40][half] = gi; pnh[drow - 40][half] = gh_reg; }
        }
        __syncthreads();
    }
}

// ---------- launcher ----------
extern "C" void kernel_launch(void* const* d_in, const int* in_sizes, int n_in,
                              void* d_out, int out_size)
{
    const float* x    = (const float*)d_in[0];
    const void*  oh   = d_in[1];
    const float* e0   = (const float*)d_in[2];
    const float* e1   = (const float*)d_in[3];
    const float* e2   = (const float*)d_in[4];
    const float* e3   = (const float*)d_in[5];
    const float* Wih1 = (const float*)d_in[6];
    const float* Whh1 = (const float*)d_in[7];
    const float* bih1 = (const float*)d_in[8];
    const float* bhh1 = (const float*)d_in[9];
    const float* Wih2 = (const float*)d_in[10];
    const float* Whh2 = (const float*)d_in[11];
    const float* bih2 = (const float*)d_in[12];
    const float* bhh2 = (const float*)d_in[13];
    const float* Wfc  = (const float*)d_in[14];
    const float* bfc  = (const float*)d_in[15];

    float* out = (float*)d_out;
    float* org = out;                              // output #1 (origin), also gi input
    float* xs  = out + (size_t)Bc * Sc * Fc;       // output #2 (decoded, time-flipped)

    embed_kernel<<<(Bc * Sc + 127) / 128, 128>>>(x, oh, e0, e1, e2, e3, org);
    gi_kernel<<<dim3(Sc / 128, Pc), 128>>>(org, Wih1, bih1, bhh1);
    gru_kernel<<<Pc, 128>>>(Whh1, bhh1, Wih2, Whh2, bih2, bhh2, Wfc, bfc, xs);
}